// round 1
// baseline (speedup 1.0000x reference)
#include <cuda_runtime.h>

// ConvCaps: votes = broadcast elementwise product, act_out = patch gather.
//
// votes[b,oh,ow,ky,kx,i,o,m,n] = poses[b,oh+ky,ow+kx,i,m,n] * K[ky,kx,i,o,m,n]
// act_out[b,oh,ow,ky,kx,i]     = activations[b,oh+ky,ow+kx,i]
//
// B=4 H=W=16 OH=OW=14 K=3 I=O=32 atoms 4x4.
// votes: 115,605,504 floats (462 MB) -> pure write-bandwidth problem.

constexpr int B = 4, H = 16, W = 16, OH = 14, OW = 14;
constexpr int IC = 32;
constexpr int SPOS = B * OH * OW;          // 784 spatial positions
constexpr int CHUNKS = 28;                 // spatial chunks per (ky,kx,i)
constexpr int SPC = SPOS / CHUNKS;         // 28 positions per block
constexpr long VOTES_FLOATS = 115605504L;  // 4*14*14*9*32*32*16
constexpr int ACT_F4 = 56448;              // 225792 / 4

// Block: 128 threads, each owns one (o,m) float4 of the weight slab for a
// fixed (ky,kx,i); weight lives in registers, pose float4 comes from L1
// (4 distinct addresses per warp -> broadcast), output is streamed out.
__global__ __launch_bounds__(128) void votes_kernel(
    const float4* __restrict__ poses,   // [B,H,W,IC,4,4] as float4: [...,IC,4]
    const float4* __restrict__ kern,    // [3,3,IC,OC,4,4] as float4
    float4* __restrict__ out)           // votes as float4
{
    const int t = threadIdx.x;          // 0..127 = o*4 + m
    int blk = blockIdx.x;               // kykx*(32*CHUNKS) + i*CHUNKS + chunk
    const int chunk = blk % CHUNKS;
    blk /= CHUNKS;
    const int i = blk % IC;
    const int kykx = blk / IC;          // 0..8
    const int ky = kykx / 3;
    const int kx = kykx - ky * 3;
    const int m = t & 3;

    // Weight float4 pinned in registers for the whole block lifetime.
    const float4 kf = kern[(kykx * IC + i) * 128 + t];

    const int s0 = chunk * SPC;
    #pragma unroll 4
    for (int s = s0; s < s0 + SPC; ++s) {
        int ow = s % OW;
        int r  = s / OW;
        int oh = r % OH;
        int b  = r / OH;
        int h = oh + ky;
        int w = ow + kx;
        // poses float4 index: (((b*H+h)*W+w)*IC + i)*4 + m
        float4 p = __ldg(&poses[(((b * H + h) * W + w) * IC + i) * 4 + m]);
        float4 v;
        v.x = p.x * kf.x;
        v.y = p.y * kf.y;
        v.z = p.z * kf.z;
        v.w = p.w * kf.w;
        // votes float4 index: ((s*9 + kykx)*IC + i)*128 + t   (max 28,901,375)
        int ofs = ((s * 9 + kykx) * IC + i) * 128 + t;
        __stcs(&out[ofs], v);
    }
}

__global__ void act_kernel(const float4* __restrict__ act,  // [B,H,W,IC] as f4
                           float4* __restrict__ out)        // act_out as f4
{
    int idx = blockIdx.x * blockDim.x + threadIdx.x;
    if (idx >= ACT_F4) return;
    int i4 = idx & 7;           // IC/4 = 8 float4 per position-tap
    int r  = idx >> 3;
    int kx = r % 3;  r /= 3;
    int ky = r % 3;  r /= 3;    // r = spatial index s
    int ow = r % OW; r /= OW;
    int oh = r % OH;
    int b  = r / OH;
    out[idx] = __ldg(&act[((b * H + oh + ky) * W + ow + kx) * 8 + i4]);
}

extern "C" void kernel_launch(void* const* d_in, const int* in_sizes, int n_in,
                              void* d_out, int out_size)
{
    const float4* poses = (const float4*)d_in[0];        // 524288 floats
    const float4* acts  = (const float4*)d_in[1];        // 32768 floats
    const float4* kern  = (const float4*)d_in[2];        // 147456 floats

    float* out_f = (float*)d_out;
    float4* votes_out = (float4*)out_f;
    float4* act_out   = (float4*)(out_f + VOTES_FLOATS);

    // 9 taps * 32 in-caps * 28 spatial chunks = 8064 blocks
    votes_kernel<<<9 * IC * CHUNKS, 128>>>(poses, kern, votes_out);
    act_kernel<<<(ACT_F4 + 255) / 256, 256>>>(acts, act_out);
}

// round 2
// speedup vs baseline: 1.0367x; 1.0367x over previous
#include <cuda_runtime.h>

// ConvCaps: votes = broadcast elementwise product, act_out = patch gather.
//
// votes[b,oh,ow,ky,kx,i,o,m,n] = poses[b,oh+ky,ow+kx,i,m,n] * K[ky,kx,i,o,m,n]
// act_out[b,oh,ow,ky,kx,i]     = activations[b,oh+ky,ow+kx,i]
//
// B=4 H=W=16 OH=OW=14 K=3 I=O=32 atoms 4x4.
// votes: 115,605,504 floats (462 MB) -> pure write-bandwidth problem.
// Single fused kernel: act blocks ride in the votes wave's slack.

constexpr int B = 4, H = 16, W = 16, OH = 14, OW = 14;
constexpr int IC = 32;
constexpr int SPOS = B * OH * OW;          // 784 spatial positions
constexpr int CHUNKS = 28;                 // spatial chunks per (ky,kx,i)
constexpr int SPC = SPOS / CHUNKS;         // 28 positions per block
constexpr long VOTES_FLOATS = 115605504L;  // 4*14*14*9*32*32*16
constexpr int ACT_F4 = 56448;              // 225792 / 4
constexpr int VBLOCKS = 9 * IC * CHUNKS;   // 8064 votes blocks
constexpr int ABLOCKS = ACT_F4 / 128;      // 441 act blocks (exact)

__global__ __launch_bounds__(128) void convcaps_fused(
    const float4* __restrict__ poses,   // [B,H,W,IC,4,4] as float4
    const float4* __restrict__ acts,    // [B,H,W,IC] as float4 (IC/4=8 per pos)
    const float4* __restrict__ kern,    // [3,3,IC,OC,4,4] as float4
    float4* __restrict__ votes_out,     // votes as float4
    float4* __restrict__ act_out)       // act_out as float4
{
    const int t = threadIdx.x;          // 0..127

    if (blockIdx.x >= VBLOCKS) {
        // ---- activation patch gather: 441 blocks * 128 threads = 56448 f4
        int idx = (blockIdx.x - VBLOCKS) * 128 + t;
        int i4 = idx & 7;               // IC/4 = 8 float4 per position-tap
        int r  = idx >> 3;
        int kx = r % 3;  r /= 3;
        int ky = r % 3;  r /= 3;        // r = output spatial index
        int ow = r % OW; r /= OW;
        int oh = r % OH;
        int b  = r / OH;
        act_out[idx] = __ldg(&acts[((b * H + oh + ky) * W + ow + kx) * 8 + i4]);
        return;
    }

    // ---- votes: each thread owns one (o,m) weight float4 for fixed (ky,kx,i)
    int blk = blockIdx.x;               // kykx*(32*CHUNKS) + i*CHUNKS + chunk
    const int chunk = blk % CHUNKS;
    blk /= CHUNKS;
    const int i = blk % IC;
    const int kykx = blk / IC;          // 0..8
    const int ky = kykx / 3;
    const int kx = kykx - ky * 3;
    const int m = t & 3;

    // Weight float4 pinned in registers for the whole block lifetime.
    const float4 kf = kern[(kykx * IC + i) * 128 + t];

    const int s0 = chunk * SPC;
    #pragma unroll 4
    for (int s = s0; s < s0 + SPC; ++s) {
        int ow = s % OW;
        int r  = s / OW;
        int oh = r % OH;
        int b  = r / OH;
        int h = oh + ky;
        int w = ow + kx;
        // poses float4 index: (((b*H+h)*W+w)*IC + i)*4 + m
        float4 p = __ldg(&poses[(((b * H + h) * W + w) * IC + i) * 4 + m]);
        float4 v;
        v.x = p.x * kf.x;
        v.y = p.y * kf.y;
        v.z = p.z * kf.z;
        v.w = p.w * kf.w;
        // votes float4 index: ((s*9 + kykx)*IC + i)*128 + t
        int ofs = ((s * 9 + kykx) * IC + i) * 128 + t;
        __stcs(&votes_out[ofs], v);
    }
}

extern "C" void kernel_launch(void* const* d_in, const int* in_sizes, int n_in,
                              void* d_out, int out_size)
{
    const float4* poses = (const float4*)d_in[0];        // 524288 floats
    const float4* acts  = (const float4*)d_in[1];        // 32768 floats
    const float4* kern  = (const float4*)d_in[2];        // 147456 floats

    float* out_f = (float*)d_out;
    float4* votes_out = (float4*)out_f;
    float4* act_out   = (float4*)(out_f + VOTES_FLOATS);

    convcaps_fused<<<VBLOCKS + ABLOCKS, 128>>>(poses, acts, kern,
                                               votes_out, act_out);
}

// round 6
// speedup vs baseline: 1.0377x; 1.0009x over previous
#include <cuda_runtime.h>

// ConvCaps: votes = broadcast elementwise product, act_out = patch gather.
//
// votes[b,oh,ow,ky,kx,i,o,m,n] = poses[b,oh+ky,ow+kx,i,m,n] * K[ky,kx,i,o,m,n]
// act_out[b,oh,ow,ky,kx,i]     = activations[b,oh+ky,ow+kx,i]
//
// B=4 H=W=16 OH=OW=14 K=3 I=O=32 atoms 4x4. votes = 462 MB of stores.
// One fused kernel; act blocks lead the grid, votes blocks are fully
// strength-reduced (each block = 2 complete output rows, zero div/mod in loop).

constexpr int B = 4, H = 16, W = 16, OH = 14, OW = 14;
constexpr int IC = 32;
constexpr long VOTES_FLOATS = 115605504L;  // 4*14*14*9*32*32*16
constexpr int ACT_F4 = 56448;              // 225792 / 4
constexpr int ROWPAIRS = B * OH / 2;       // 28 row-pairs (chunk = 2 rows)
constexpr int VBLOCKS = 9 * IC * ROWPAIRS; // 8064
constexpr int ABLOCKS = ACT_F4 / 128;      // 441 (exact)
constexpr int OUT_STRIDE_S = 9 * IC * 128; // float4 stride between spatial s

__global__ __launch_bounds__(128) void convcaps_fused(
    const float4* __restrict__ poses,   // [B,H,W,IC,4,4] as float4
    const float4* __restrict__ acts,    // [B,H,W,IC] as float4 (8 per pos)
    const float4* __restrict__ kern,    // [3,3,IC,OC,4,4] as float4
    float4* __restrict__ votes_out,
    float4* __restrict__ act_out)
{
    const int t = threadIdx.x;          // 0..127 = o*4 + m

    if (blockIdx.x < ABLOCKS) {
        // ---- activation patch gather (tiny; hides under wave-1 spin-up)
        int idx = blockIdx.x * 128 + t;
        int i4 = idx & 7;
        int r  = idx >> 3;
        int kx = r % 3;  r /= 3;
        int ky = r % 3;  r /= 3;
        int ow = r % OW; r /= OW;
        int oh = r % OH;
        int b  = r / OH;
        act_out[idx] = __ldg(&acts[((b * H + oh + ky) * W + ow + kx) * 8 + i4]);
        return;
    }

    // ---- votes
    int blk = blockIdx.x - ABLOCKS;     // kykx*(IC*ROWPAIRS) + i*ROWPAIRS + rp
    const int rp = blk % ROWPAIRS;
    blk /= ROWPAIRS;
    const int i = blk % IC;
    const int kykx = blk / IC;          // 0..8
    const int ky = kykx / 3;
    const int kx = kykx - ky * 3;
    const int m = t & 3;

    // Weight float4 pinned in registers.
    const float4 kf = kern[(kykx * IC + i) * 128 + t];

    // This block covers output rows row0, row0+1 (never straddles batch b).
    const int row0 = rp * 2;            // global output row index (b*OH + oh)
    const int b   = row0 / OH;
    const int oh0 = row0 - b * OH;

    // Pose pointer at (b, oh0+ky, kx, i, m); +128 f4 per ow, +2048 f4 per row.
    const float4* pp =
        poses + ((((b * H + oh0 + ky) * W + kx) * IC + i) * 4 + m);
    // Output pointer at s = row0*OW; +OUT_STRIDE_S f4 per s.
    float4* op = votes_out + (((long)(row0 * OW) * 9 + kykx) * IC + i) * 128 + t;

    #pragma unroll
    for (int r = 0; r < 2; ++r) {
        #pragma unroll
        for (int ow = 0; ow < OW; ++ow) {
            float4 p = __ldg(pp + ow * (IC * 4));
            float4 v;
            v.x = p.x * kf.x;
            v.y = p.y * kf.y;
            v.z = p.z * kf.z;
            v.w = p.w * kf.w;
            __stcs(op + ow * OUT_STRIDE_S, v);
        }
        pp += W * IC * 4;               // next input row
        op += (long)OW * OUT_STRIDE_S;  // next output row
    }
}

extern "C" void kernel_launch(void* const* d_in, const int* in_sizes, int n_in,
                              void* d_out, int out_size)
{
    const float4* poses = (const float4*)d_in[0];
    const float4* acts  = (const float4*)d_in[1];
    const float4* kern  = (const float4*)d_in[2];

    float* out_f = (float*)d_out;
    float4* votes_out = (float4*)out_f;
    float4* act_out   = (float4*)(out_f + VOTES_FLOATS);

    convcaps_fused<<<ABLOCKS + VBLOCKS, 128>>>(poses, acts, kern,
                                               votes_out, act_out);
}

// round 10
// speedup vs baseline: 1.0566x; 1.0183x over previous
#include <cuda_runtime.h>

// ConvCaps: votes = broadcast elementwise product, act_out = patch gather.
//
// votes[b,oh,ow,ky,kx,i,o,m,n] = poses[b,oh+ky,ow+kx,i,m,n] * K[ky,kx,i,o,m,n]
// act_out[b,oh,ow,ky,kx,i]     = activations[b,oh+ky,ow+kx,i]
//
// B=4 H=W=16 OH=OW=14 K=3 I=O=32 atoms 4x4. votes = 462 MB of stores ->
// DRAM-write-bound. Grid is ordered (rowpair, kykx, i) so the ~288
// consecutively-scheduled blocks tile one contiguous 576KB output region in
// lockstep (DRAM open-page locality), instead of scattering 2KB chunks at
// 1.15MB strides.

constexpr int B = 4, H = 16, W = 16, OH = 14, OW = 14;
constexpr int IC = 32;
constexpr long VOTES_FLOATS = 115605504L;  // 4*14*14*9*32*32*16
constexpr int ACT_F4 = 56448;              // 225792 / 4
constexpr int ROWPAIRS = B * OH / 2;       // 28 (block = 2 output rows)
constexpr int SLABS = 9 * IC;              // 288 (kykx, i) weight slabs
constexpr int VBLOCKS = SLABS * ROWPAIRS;  // 8064
constexpr int ABLOCKS = ACT_F4 / 128;      // 441 (exact)
constexpr int OUT_STRIDE_S = 9 * IC * 128; // float4 stride between spatial s

__global__ __launch_bounds__(128) void convcaps_fused(
    const float4* __restrict__ poses,   // [B,H,W,IC,4,4] as float4
    const float4* __restrict__ acts,    // [B,H,W,IC] as float4 (8 per pos)
    const float4* __restrict__ kern,    // [3,3,IC,OC,4,4] as float4
    float4* __restrict__ votes_out,
    float4* __restrict__ act_out)
{
    const int t = threadIdx.x;          // 0..127 = o*4 + m

    if (blockIdx.x < ABLOCKS) {
        // ---- activation patch gather (tiny; hides under wave-1 spin-up)
        int idx = blockIdx.x * 128 + t;
        int i4 = idx & 7;
        int r  = idx >> 3;
        int kx = r % 3;  r /= 3;
        int ky = r % 3;  r /= 3;
        int ow = r % OW; r /= OW;
        int oh = r % OH;
        int b  = r / OH;
        act_out[idx] = __ldg(&acts[((b * H + oh + ky) * W + ow + kx) * 8 + i4]);
        return;
    }

    // ---- votes: grid order (rowpair major, then kykx, then i fastest)
    int blk = blockIdx.x - ABLOCKS;
    const int slab = blk % SLABS;       // kykx*IC + i
    const int rp   = blk / SLABS;
    const int i    = slab % IC;
    const int kykx = slab / IC;         // 0..8
    const int ky = kykx / 3;
    const int kx = kykx - ky * 3;
    const int m = t & 3;

    // Weight float4 pinned in registers for the whole block lifetime.
    const float4 kf = kern[slab * 128 + t];

    // This block covers output rows row0, row0+1 (never straddles batch b).
    const int row0 = rp * 2;            // global output row index (b*OH + oh)
    const int b   = row0 / OH;
    const int oh0 = row0 - b * OH;

    // Pose pointer at (b, oh0+ky, kx, i, m); +128 f4 per ow, +2048 f4 per row.
    const float4* pp =
        poses + ((((b * H + oh0 + ky) * W + kx) * IC + i) * 4 + m);
    // Output pointer at s = row0*OW; +OUT_STRIDE_S f4 per s.
    float4* op = votes_out + (((long)(row0 * OW) * 9 + kykx) * IC + i) * 128 + t;

    #pragma unroll
    for (int r = 0; r < 2; ++r) {
        #pragma unroll
        for (int ow = 0; ow < OW; ++ow) {
            float4 p = __ldg(pp + ow * (IC * 4));
            float4 v;
            v.x = p.x * kf.x;
            v.y = p.y * kf.y;
            v.z = p.z * kf.z;
            v.w = p.w * kf.w;
            __stcs(op + ow * OUT_STRIDE_S, v);
        }
        pp += W * IC * 4;               // next input row
        op += (long)OW * OUT_STRIDE_S;  // next output row
    }
}

extern "C" void kernel_launch(void* const* d_in, const int* in_sizes, int n_in,
                              void* d_out, int out_size)
{
    const float4* poses = (const float4*)d_in[0];
    const float4* acts  = (const float4*)d_in[1];
    const float4* kern  = (const float4*)d_in[2];

    float* out_f = (float*)d_out;
    float4* votes_out = (float4*)out_f;
    float4* act_out   = (float4*)(out_f + VOTES_FLOATS);

    convcaps_fused<<<ABLOCKS + VBLOCKS, 128>>>(poses, acts, kern,
                                               votes_out, act_out);
}